// round 14
// baseline (speedup 1.0000x reference)
#include <cuda_runtime.h>
#include <math.h>

#define BATCH 2
#define CH 64
#define IMG 448
#define HW 200704            // 448*448
#define CHW 12845056         // 64*HW
#define P2 196
#define TG 56
#define TG2 3136
#define EPSV 1e-5f
#define KSPLIT 128
#define SPLIT_LEN 512        // 65536/128
#define WMN 38416            // 196*196
#define WGN 9834496          // 3136*3136

// ---------------- scratch (device globals; no allocations allowed) ----------
__device__ float g_q[BATCH * CHW];
__device__ float g_k[BATCH * CHW];
__device__ float g_v[BATCH * CHW];
__device__ float g_hp[BATCH * CHW];
__device__ float g_wm[BATCH * WMN];
__device__ float g_wmpart[BATCH * KSPLIT * WMN];
__device__ float g_wg[BATCH * WGN];
__device__ float g_qg[BATCH * CH * TG2];
__device__ float g_kg[BATCH * CH * TG2];
__device__ float g_vg[BATCH * CH * TG2];
__device__ float g_hgpart[BATCH * 4 * CH * TG2];
__device__ float g_hg[BATCH * CH * TG2];
__device__ float g_red[4096];   // [2 arrays][batch][1024 blocks]
__device__ float g_stats[4];    // mean,rstd per batch

// ---------------- 1) GroupNorm stats: partial reduction ---------------------
__global__ void k_red1(const float* __restrict__ x) {
    int b = blockIdx.y;
    int blk = blockIdx.x;                 // 0..1023
    const float* p = x + (size_t)b * CHW + (size_t)blk * 12544;
    float s = 0.f, s2 = 0.f;
    for (int i = threadIdx.x; i < 12544; i += 256) {
        float v = p[i];
        s += v; s2 += v * v;
    }
    __shared__ float sh0[256], sh1[256];
    sh0[threadIdx.x] = s; sh1[threadIdx.x] = s2;
    __syncthreads();
    for (int o = 128; o > 0; o >>= 1) {
        if (threadIdx.x < o) {
            sh0[threadIdx.x] += sh0[threadIdx.x + o];
            sh1[threadIdx.x] += sh1[threadIdx.x + o];
        }
        __syncthreads();
    }
    if (threadIdx.x == 0) {
        g_red[b * 1024 + blk] = sh0[0];
        g_red[2048 + b * 1024 + blk] = sh1[0];
    }
}

// ---------------- 2) finalize mean / rstd -----------------------------------
__global__ void k_red2() {
    int b = blockIdx.x;
    float s = 0.f, s2 = 0.f;
    for (int i = threadIdx.x; i < 1024; i += 256) {
        s += g_red[b * 1024 + i];
        s2 += g_red[2048 + b * 1024 + i];
    }
    __shared__ float sh0[256], sh1[256];
    sh0[threadIdx.x] = s; sh1[threadIdx.x] = s2;
    __syncthreads();
    for (int o = 128; o > 0; o >>= 1) {
        if (threadIdx.x < o) {
            sh0[threadIdx.x] += sh0[threadIdx.x + o];
            sh1[threadIdx.x] += sh1[threadIdx.x + o];
        }
        __syncthreads();
    }
    if (threadIdx.x == 0) {
        float mean = sh0[0] / (float)CHW;
        float var = sh1[0] / (float)CHW - mean * mean;
        g_stats[b * 2 + 0] = mean;
        g_stats[b * 2 + 1] = rsqrtf(var + EPSV);
    }
}

// ---------------- 3) fused GroupNorm + QKV (three 64x64 GEMMs over pixels) --
// Out[m, n] = W[m,:] . xn[:, n] + bias[m]; grid.y selects q/k/v.
__global__ __launch_bounds__(256) void k_gnqkv(
    const float* __restrict__ x,
    const float* __restrict__ gnw, const float* __restrict__ gnb,
    const float* __restrict__ qw, const float* __restrict__ qb,
    const float* __restrict__ kw, const float* __restrict__ kb,
    const float* __restrict__ vw, const float* __restrict__ vb) {
    __shared__ float Wt[64][64];    // [k][m]
    __shared__ float Xn[64][128];   // [k][n]
    int mt = blockIdx.y;
    int n0 = blockIdx.x * 128;      // global pixel index across batches
    int b = n0 / HW;
    int pix0 = n0 % HW;
    const float* W    = (mt == 0) ? qw : (mt == 1) ? kw : vw;
    const float* bias = (mt == 0) ? qb : (mt == 1) ? kb : vb;
    float* out = ((mt == 0) ? g_q : (mt == 1) ? g_k : g_v) + (size_t)b * CHW + pix0;

    float mean = g_stats[b * 2 + 0];
    float rstd = g_stats[b * 2 + 1];
    int tx = threadIdx.x, ty = threadIdx.y;
    int tid = ty * 16 + tx;

    for (int e = tid; e < 4096; e += 256) {
        int m = e >> 6, k = e & 63;
        Wt[k][m] = W[e];            // W is [m][k] row-major
    }
    const float* xb = x + (size_t)b * CHW + pix0;
    for (int e = tid; e < 8192; e += 256) {
        int k = e >> 7, nl = e & 127;
        float v = xb[(size_t)k * HW + nl];
        Xn[k][nl] = (v - mean) * rstd * gnw[k] + gnb[k];
    }
    __syncthreads();

    float acc[4][8];
#pragma unroll
    for (int i = 0; i < 4; i++)
#pragma unroll
        for (int j = 0; j < 8; j++) acc[i][j] = 0.f;

#pragma unroll 8
    for (int k = 0; k < 64; k++) {
        float a[4], bb[8];
#pragma unroll
        for (int i = 0; i < 4; i++) a[i] = Wt[k][ty + 16 * i];
#pragma unroll
        for (int j = 0; j < 8; j++) bb[j] = Xn[k][tx + 16 * j];
#pragma unroll
        for (int i = 0; i < 4; i++)
#pragma unroll
            for (int j = 0; j < 8; j++) acc[i][j] += a[i] * bb[j];
    }

#pragma unroll
    for (int i = 0; i < 4; i++) {
        int m = ty + 16 * i;
        float bv = bias[m];
#pragma unroll
        for (int j = 0; j < 8; j++)
            out[(size_t)m * HW + tx + 16 * j] = acc[i][j] + bv;
    }
}

// ---------------- 4) 8x8 average pool of q,k,v ------------------------------
__global__ void k_pool() {
    int idx = blockIdx.x * 256 + threadIdx.x;     // 0 .. B*C*TG2-1
    if (idx >= BATCH * CH * TG2) return;
    int q = idx % TG2;
    int c = (idx / TG2) % CH;
    int b = idx / (TG2 * CH);
    int py = q / TG, px = q % TG;
    size_t base = (size_t)b * CHW + (size_t)c * HW + (size_t)(py * 8) * IMG + px * 8;
    float sq = 0.f, sk = 0.f, sv = 0.f;
#pragma unroll
    for (int dy = 0; dy < 8; dy++) {
        size_t r = base + (size_t)dy * IMG;
#pragma unroll
        for (int dx = 0; dx < 8; dx++) {
            sq += g_q[r + dx]; sk += g_k[r + dx]; sv += g_v[r + dx];
        }
    }
    g_qg[idx] = sq * (1.f / 64.f);
    g_kg[idx] = sk * (1.f / 64.f);
    g_vg[idx] = sv * (1.f / 64.f);
}

// ---------------- 5) patch gram partials: wm_part = Qf^T Kf over s-split ----
__global__ __launch_bounds__(256) void k_wmgram() {
    int quarter = blockIdx.x & 3;     // p-quarter (49 each)
    int split = blockIdx.x >> 2;      // 0..127
    int b = blockIdx.y;
    const float* qf = g_q + (size_t)b * CHW;
    const float* kf = g_k + (size_t)b * CHW;
    __shared__ float qs[16][64];      // [s][p], 49 valid cols
    __shared__ float ks[16][208];     // [s][q], 196 valid cols
    int tx = threadIdx.x, ty = threadIdx.y;
    int tid = ty * 16 + tx;
    int p0 = quarter * 49;
    int s0 = split * SPLIT_LEN;

    float acc[4][13];
#pragma unroll
    for (int i = 0; i < 4; i++)
#pragma unroll
        for (int j = 0; j < 13; j++) acc[i][j] = 0.f;

    for (int kc = 0; kc < SPLIT_LEN; kc += 16) {
        for (int e = tid; e < 16 * 49; e += 256) {
            int r = e / 49, p = e % 49;
            qs[r][p] = qf[(size_t)(s0 + kc + r) * P2 + p0 + p];
        }
        for (int e = tid; e < 16 * P2; e += 256) {
            int r = e / P2, qq = e % P2;
            ks[r][qq] = kf[(size_t)(s0 + kc + r) * P2 + qq];
        }
        __syncthreads();
#pragma unroll 4
        for (int r = 0; r < 16; r++) {
            float a[4], bb[13];
#pragma unroll
            for (int i = 0; i < 4; i++) a[i] = qs[r][ty + 16 * i];
#pragma unroll
            for (int j = 0; j < 13; j++) bb[j] = ks[r][tx + 16 * j];
#pragma unroll
            for (int i = 0; i < 4; i++)
#pragma unroll
                for (int j = 0; j < 13; j++) acc[i][j] += a[i] * bb[j];
        }
        __syncthreads();
    }

    float* out = g_wmpart + ((size_t)(b * KSPLIT + split)) * WMN;
#pragma unroll
    for (int i = 0; i < 4; i++) {
        int pl = ty + 16 * i;
        if (pl < 49) {
#pragma unroll
            for (int j = 0; j < 13; j++) {
                int q = tx + 16 * j;
                if (q < P2) out[(size_t)(p0 + pl) * P2 + q] = acc[i][j];
            }
        }
    }
}

// ---------------- 6) reduce split partials + scale + softmax (rows of 196) --
__global__ void k_wmsoftmax() {
    int row = blockIdx.x;             // b*196 + p
    int b = row / P2;
    int p = row % P2;
    int t = threadIdx.x;
    float val = 0.f;
    if (t < P2) {
        const float* part = g_wmpart + (size_t)b * KSPLIT * WMN + (size_t)p * P2 + t;
        float s = 0.f;
        for (int sp = 0; sp < KSPLIT; sp++) s += part[(size_t)sp * WMN];
        val = s * (1.f / 256.f);      // S^-0.5, S=65536
    }
    __shared__ float sh[256];
    sh[t] = (t < P2) ? val : -INFINITY;
    __syncthreads();
    for (int o = 128; o > 0; o >>= 1) {
        if (t < o) sh[t] = fmaxf(sh[t], sh[t + o]);
        __syncthreads();
    }
    float mx = sh[0];
    __syncthreads();
    float e = (t < P2) ? expf(val - mx) : 0.f;
    sh[t] = e;
    __syncthreads();
    for (int o = 128; o > 0; o >>= 1) {
        if (t < o) sh[t] += sh[t + o];
        __syncthreads();
    }
    float inv = 1.f / sh[0];
    if (t < P2) g_wm[(size_t)row * P2 + t] = e * inv;
}

// ---------------- 7) hp[s,q] = sum_k vf[s,k] * wm[q,k] ----------------------
__global__ __launch_bounds__(256) void k_hp() {
    int b = blockIdx.y;
    int s0 = blockIdx.x * 64;
    const float* vf = g_v + (size_t)b * CHW;
    const float* wm = g_wm + (size_t)b * WMN;
    __shared__ float vs[28][65];      // [k][s_local]
    __shared__ float ws[28][209];     // [k][q]
    int tx = threadIdx.x, ty = threadIdx.y;
    int tid = ty * 16 + tx;

    float acc[4][13];
#pragma unroll
    for (int i = 0; i < 4; i++)
#pragma unroll
        for (int j = 0; j < 13; j++) acc[i][j] = 0.f;

    for (int k0 = 0; k0 < P2; k0 += 28) {
        for (int e = tid; e < 64 * 28; e += 256) {
            int sl = e / 28, kk = e % 28;
            vs[kk][sl] = vf[(size_t)(s0 + sl) * P2 + k0 + kk];
        }
        for (int e = tid; e < P2 * 28; e += 256) {
            int q = e / 28, kk = e % 28;
            ws[kk][q] = wm[(size_t)q * P2 + k0 + kk];
        }
        __syncthreads();
#pragma unroll 4
        for (int kk = 0; kk < 28; kk++) {
            float a[4], bb[13];
#pragma unroll
            for (int i = 0; i < 4; i++) a[i] = vs[kk][ty + 16 * i];
#pragma unroll
            for (int j = 0; j < 13; j++) bb[j] = ws[kk][tx + 16 * j];
#pragma unroll
            for (int i = 0; i < 4; i++)
#pragma unroll
                for (int j = 0; j < 13; j++) acc[i][j] += a[i] * bb[j];
        }
        __syncthreads();
    }

    float* hp = g_hp + (size_t)b * CHW + (size_t)s0 * P2;
#pragma unroll
    for (int i = 0; i < 4; i++) {
        int sl = ty + 16 * i;
#pragma unroll
        for (int j = 0; j < 13; j++) {
            int q = tx + 16 * j;
            if (q < P2) hp[(size_t)sl * P2 + q] = acc[i][j];
        }
    }
}

// ---------------- 8) global gram: wg[p,q] = (1/8) sum_c qg[c,p] kg[c,q] -----
__global__ __launch_bounds__(256) void k_wggram() {
    int pt = blockIdx.x / 49;
    int qt = blockIdx.x % 49;
    int b = blockIdx.y;
    const float* qg = g_qg + (size_t)b * CH * TG2;
    const float* kg = g_kg + (size_t)b * CH * TG2;
    __shared__ float qs[64][64];      // [c][p]
    __shared__ float ks[64][64];      // [c][q]
    int tx = threadIdx.x, ty = threadIdx.y;
    int tid = ty * 16 + tx;
    for (int e = tid; e < 4096; e += 256) {
        int c = e >> 6, l = e & 63;
        qs[c][l] = qg[(size_t)c * TG2 + pt * 64 + l];
        ks[c][l] = kg[(size_t)c * TG2 + qt * 64 + l];
    }
    __syncthreads();
    float acc[4][4];
#pragma unroll
    for (int i = 0; i < 4; i++)
#pragma unroll
        for (int j = 0; j < 4; j++) acc[i][j] = 0.f;
#pragma unroll 8
    for (int k = 0; k < 64; k++) {
        float a[4], bb[4];
#pragma unroll
        for (int i = 0; i < 4; i++) a[i] = qs[k][ty + 16 * i];
#pragma unroll
        for (int j = 0; j < 4; j++) bb[j] = ks[k][tx + 16 * j];
#pragma unroll
        for (int i = 0; i < 4; i++)
#pragma unroll
            for (int j = 0; j < 4; j++) acc[i][j] += a[i] * bb[j];
    }
    float* out = g_wg + (size_t)b * WGN;
#pragma unroll
    for (int i = 0; i < 4; i++) {
        int p = pt * 64 + ty + 16 * i;
#pragma unroll
        for (int j = 0; j < 4; j++) {
            int q = qt * 64 + tx + 16 * j;
            out[(size_t)p * TG2 + q] = acc[i][j] * 0.125f;   // c^-0.5
        }
    }
}

// ---------------- 9) softmax over rows of length 3136 -----------------------
__global__ void k_wgsoftmax() {
    int row = blockIdx.x;             // 0 .. B*TG2-1
    float* w = g_wg + (size_t)row * TG2;
    int t = threadIdx.x;
    float vals[13];
    float mx = -INFINITY;
#pragma unroll
    for (int i = 0; i < 13; i++) {
        int idx = t + 256 * i;
        vals[i] = (idx < TG2) ? w[idx] : -INFINITY;
        mx = fmaxf(mx, vals[i]);
    }
    __shared__ float sh[256];
    sh[t] = mx;
    __syncthreads();
    for (int o = 128; o > 0; o >>= 1) {
        if (t < o) sh[t] = fmaxf(sh[t], sh[t + o]);
        __syncthreads();
    }
    mx = sh[0];
    __syncthreads();
    float s = 0.f;
#pragma unroll
    for (int i = 0; i < 13; i++) {
        int idx = t + 256 * i;
        if (idx < TG2) {
            vals[i] = expf(vals[i] - mx);
            s += vals[i];
        }
    }
    sh[t] = s;
    __syncthreads();
    for (int o = 128; o > 0; o >>= 1) {
        if (t < o) sh[t] += sh[t + o];
        __syncthreads();
    }
    float inv = 1.f / sh[0];
#pragma unroll
    for (int i = 0; i < 13; i++) {
        int idx = t + 256 * i;
        if (idx < TG2) w[idx] = vals[i] * inv;
    }
}

// ---------------- 10) hg partials: hg[c,q] = sum_k vg[c,k] wg[q,k] ----------
__global__ __launch_bounds__(256) void k_hg() {
    int qt = blockIdx.x / 4;
    int sp = blockIdx.x % 4;          // k-split
    int b = blockIdx.y;
    const float* vg = g_vg + (size_t)b * CH * TG2;
    const float* wg = g_wg + (size_t)b * WGN;
    __shared__ float vs[16][65];      // [k][c]
    __shared__ float ws[16][65];      // [k][q_local]
    int tx = threadIdx.x, ty = threadIdx.y;
    int tid = ty * 16 + tx;

    float acc[4][4];
#pragma unroll
    for (int i = 0; i < 4; i++)
#pragma unroll
        for (int j = 0; j < 4; j++) acc[i][j] = 0.f;

    int kbase = sp * 784;
    for (int k0 = kbase; k0 < kbase + 784; k0 += 16) {
        for (int e = tid; e < 64 * 16; e += 256) {
            int c = e / 16, kk = e % 16;
            vs[kk][c] = vg[(size_t)c * TG2 + k0 + kk];
        }
        for (int e = tid; e < 64 * 16; e += 256) {
            int ql = e / 16, kk = e % 16;
            ws[kk][ql] = wg[(size_t)(qt * 64 + ql) * TG2 + k0 + kk];
        }
        __syncthreads();
#pragma unroll 4
        for (int kk = 0; kk < 16; kk++) {
            float a[4], bb[4];
#pragma unroll
            for (int i = 0; i < 4; i++) a[i] = vs[kk][ty + 16 * i];
#pragma unroll
            for (int j = 0; j < 4; j++) bb[j] = ws[kk][tx + 16 * j];
#pragma unroll
            for (int i = 0; i < 4; i++)
#pragma unroll
                for (int j = 0; j < 4; j++) acc[i][j] += a[i] * bb[j];
        }
        __syncthreads();
    }

    float* out = g_hgpart + (size_t)(b * 4 + sp) * CH * TG2;
#pragma unroll
    for (int i = 0; i < 4; i++) {
        int c = ty + 16 * i;
#pragma unroll
        for (int j = 0; j < 4; j++) {
            int q = qt * 64 + tx + 16 * j;
            out[(size_t)c * TG2 + q] = acc[i][j];
        }
    }
}

__global__ void k_hgreduce() {
    int idx = blockIdx.x * 256 + threadIdx.x;
    if (idx >= BATCH * CH * TG2) return;
    int b = idx / (CH * TG2);
    int r = idx % (CH * TG2);
    float s = 0.f;
#pragma unroll
    for (int sp = 0; sp < 4; sp++)
        s += g_hgpart[(size_t)(b * 4 + sp) * CH * TG2 + r];
    g_hg[idx] = s;
}

// ---------------- 11) final: out = x + proj_w @ (0.75 hp + 0.25 up(hg)) -----
__global__ __launch_bounds__(256) void k_final(
    const float* __restrict__ x,
    const float* __restrict__ pw,
    float* __restrict__ out) {
    __shared__ float Wt[64][64];      // [k][m]
    __shared__ float Hs[64][128];     // [k][n]
    int n0 = blockIdx.x * 128;
    int b = n0 / HW;
    int pix0 = n0 % HW;
    int tx = threadIdx.x, ty = threadIdx.y;
    int tid = ty * 16 + tx;

    for (int e = tid; e < 4096; e += 256) {
        int m = e >> 6, k = e & 63;
        Wt[k][m] = pw[e];
    }
    for (int e = tid; e < 8192; e += 256) {
        int k = e >> 7, nl = e & 127;
        int pix = pix0 + nl;
        int py = pix / IMG, px = pix % IMG;
        float hpv = g_hp[(size_t)b * CHW + (size_t)k * HW + pix];
        float hgv = g_hg[((size_t)b * CH + k) * TG2 + (py >> 3) * TG + (px >> 3)];
        Hs[k][nl] = 0.75f * hpv + 0.25f * hgv;
    }
    __syncthreads();

    float acc[4][8];
#pragma unroll
    for (int i = 0; i < 4; i++)
#pragma unroll
        for (int j = 0; j < 8; j++) acc[i][j] = 0.f;
#pragma unroll 8
    for (int k = 0; k < 64; k++) {
        float a[4], bb[8];
#pragma unroll
        for (int i = 0; i < 4; i++) a[i] = Wt[k][ty + 16 * i];
#pragma unroll
        for (int j = 0; j < 8; j++) bb[j] = Hs[k][tx + 16 * j];
#pragma unroll
        for (int i = 0; i < 4; i++)
#pragma unroll
            for (int j = 0; j < 8; j++) acc[i][j] += a[i] * bb[j];
    }

#pragma unroll
    for (int i = 0; i < 4; i++) {
        int m = ty + 16 * i;
#pragma unroll
        for (int j = 0; j < 8; j++) {
            size_t idx = (size_t)b * CHW + (size_t)m * HW + pix0 + tx + 16 * j;
            out[idx] = x[idx] + acc[i][j];
        }
    }
}

// ---------------- launch -----------------------------------------------------
extern "C" void kernel_launch(void* const* d_in, const int* in_sizes, int n_in,
                              void* d_out, int out_size) {
    const float* x   = (const float*)d_in[0];
    const float* gnw = (const float*)d_in[1];
    const float* gnb = (const float*)d_in[2];
    const float* qw  = (const float*)d_in[3];
    const float* qb  = (const float*)d_in[4];
    const float* kw  = (const float*)d_in[5];
    const float* kb  = (const float*)d_in[6];
    const float* vw  = (const float*)d_in[7];
    const float* vb  = (const float*)d_in[8];
    const float* pw  = (const float*)d_in[9];
    float* out = (float*)d_out;

    k_red1<<<dim3(1024, BATCH), 256>>>(x);
    k_red2<<<BATCH, 256>>>();
    k_gnqkv<<<dim3(3136, 3), dim3(16, 16)>>>(x, gnw, gnb, qw, qb, kw, kb, vw, vb);
    k_pool<<<1568, 256>>>();
    k_wmgram<<<dim3(4 * KSPLIT, BATCH), dim3(16, 16)>>>();
    k_wmsoftmax<<<BATCH * P2, 256>>>();
    k_hp<<<dim3(1024, BATCH), dim3(16, 16)>>>();
    k_wggram<<<dim3(49 * 49, BATCH), dim3(16, 16)>>>();
    k_wgsoftmax<<<BATCH * TG2, 256>>>();
    k_hg<<<dim3(49 * 4, BATCH), dim3(16, 16)>>>();
    k_hgreduce<<<1568, 256>>>();
    k_final<<<3136, dim3(16, 16)>>>(x, pw, out);
}

// round 15
// speedup vs baseline: 1.0018x; 1.0018x over previous
#include <cuda_runtime.h>
#include <math.h>

#define BATCH 2
#define CH 64
#define IMG 448
#define HW 200704            // 448*448
#define CHW 12845056         // 64*HW
#define P2 196
#define TG 56
#define TG2 3136
#define EPSV 1e-5f
#define KSPLIT 128
#define SPLIT_LEN 512        // 65536/128
#define WMN 38416            // 196*196
#define WGN 9834496          // 3136*3136

// ---------------- scratch (device globals; no allocations allowed) ----------
__device__ float g_q[BATCH * CHW];
__device__ float g_k[BATCH * CHW];
__device__ float g_v[BATCH * CHW];
__device__ float g_hp[BATCH * CHW];
__device__ float g_wm[BATCH * WMN];
__device__ float g_wmpart[BATCH * KSPLIT * WMN];
__device__ float g_wg[BATCH * WGN];
__device__ float g_qg[BATCH * CH * TG2];
__device__ float g_kg[BATCH * CH * TG2];
__device__ float g_vg[BATCH * CH * TG2];
__device__ float g_hgpart[BATCH * 4 * CH * TG2];
__device__ float g_hg[BATCH * CH * TG2];
__device__ float g_red[4096];   // [2 arrays][batch][1024 blocks]
__device__ float g_stats[4];    // mean,rstd per batch

// ---------------- 1) GroupNorm stats: partial reduction ---------------------
__global__ void k_red1(const float* __restrict__ x) {
    int b = blockIdx.y;
    int blk = blockIdx.x;                 // 0..1023
    const float* p = x + (size_t)b * CHW + (size_t)blk * 12544;
    float s = 0.f, s2 = 0.f;
    for (int i = threadIdx.x; i < 12544; i += 256) {
        float v = p[i];
        s += v; s2 += v * v;
    }
    __shared__ float sh0[256], sh1[256];
    sh0[threadIdx.x] = s; sh1[threadIdx.x] = s2;
    __syncthreads();
    for (int o = 128; o > 0; o >>= 1) {
        if (threadIdx.x < o) {
            sh0[threadIdx.x] += sh0[threadIdx.x + o];
            sh1[threadIdx.x] += sh1[threadIdx.x + o];
        }
        __syncthreads();
    }
    if (threadIdx.x == 0) {
        g_red[b * 1024 + blk] = sh0[0];
        g_red[2048 + b * 1024 + blk] = sh1[0];
    }
}

// ---------------- 2) finalize mean / rstd -----------------------------------
__global__ void k_red2() {
    int b = blockIdx.x;
    float s = 0.f, s2 = 0.f;
    for (int i = threadIdx.x; i < 1024; i += 256) {
        s += g_red[b * 1024 + i];
        s2 += g_red[2048 + b * 1024 + i];
    }
    __shared__ float sh0[256], sh1[256];
    sh0[threadIdx.x] = s; sh1[threadIdx.x] = s2;
    __syncthreads();
    for (int o = 128; o > 0; o >>= 1) {
        if (threadIdx.x < o) {
            sh0[threadIdx.x] += sh0[threadIdx.x + o];
            sh1[threadIdx.x] += sh1[threadIdx.x + o];
        }
        __syncthreads();
    }
    if (threadIdx.x == 0) {
        float mean = sh0[0] / (float)CHW;
        float var = sh1[0] / (float)CHW - mean * mean;
        g_stats[b * 2 + 0] = mean;
        g_stats[b * 2 + 1] = rsqrtf(var + EPSV);
    }
}

// ---------------- 3) fused GroupNorm + QKV (three 64x64 GEMMs over pixels) --
// Out[m, n] = W[m,:] . xn[:, n] + bias[m]; grid.y selects q/k/v.
__global__ __launch_bounds__(256) void k_gnqkv(
    const float* __restrict__ x,
    const float* __restrict__ gnw, const float* __restrict__ gnb,
    const float* __restrict__ qw, const float* __restrict__ qb,
    const float* __restrict__ kw, const float* __restrict__ kb,
    const float* __restrict__ vw, const float* __restrict__ vb) {
    __shared__ float Wt[64][64];    // [k][m]
    __shared__ float Xn[64][128];   // [k][n]
    int mt = blockIdx.y;
    int n0 = blockIdx.x * 128;      // global pixel index across batches
    int b = n0 / HW;
    int pix0 = n0 % HW;
    const float* W    = (mt == 0) ? qw : (mt == 1) ? kw : vw;
    const float* bias = (mt == 0) ? qb : (mt == 1) ? kb : vb;
    float* out = ((mt == 0) ? g_q : (mt == 1) ? g_k : g_v) + (size_t)b * CHW + pix0;

    float mean = g_stats[b * 2 + 0];
    float rstd = g_stats[b * 2 + 1];
    int tx = threadIdx.x, ty = threadIdx.y;
    int tid = ty * 16 + tx;

    for (int e = tid; e < 4096; e += 256) {
        int m = e >> 6, k = e & 63;
        Wt[k][m] = W[e];            // W is [m][k] row-major
    }
    const float* xb = x + (size_t)b * CHW + pix0;
    for (int e = tid; e < 8192; e += 256) {
        int k = e >> 7, nl = e & 127;
        float v = xb[(size_t)k * HW + nl];
        Xn[k][nl] = (v - mean) * rstd * gnw[k] + gnb[k];
    }
    __syncthreads();

    float acc[4][8];
#pragma unroll
    for (int i = 0; i < 4; i++)
#pragma unroll
        for (int j = 0; j < 8; j++) acc[i][j] = 0.f;

#pragma unroll 8
    for (int k = 0; k < 64; k++) {
        float a[4], bb[8];
#pragma unroll
        for (int i = 0; i < 4; i++) a[i] = Wt[k][ty + 16 * i];
#pragma unroll
        for (int j = 0; j < 8; j++) bb[j] = Xn[k][tx + 16 * j];
#pragma unroll
        for (int i = 0; i < 4; i++)
#pragma unroll
            for (int j = 0; j < 8; j++) acc[i][j] += a[i] * bb[j];
    }

#pragma unroll
    for (int i = 0; i < 4; i++) {
        int m = ty + 16 * i;
        float bv = bias[m];
#pragma unroll
        for (int j = 0; j < 8; j++)
            out[(size_t)m * HW + tx + 16 * j] = acc[i][j] + bv;
    }
}

// ---------------- 4) 8x8 average pool of q,k,v ------------------------------
__global__ void k_pool() {
    int idx = blockIdx.x * 256 + threadIdx.x;     // 0 .. B*C*TG2-1
    if (idx >= BATCH * CH * TG2) return;
    int q = idx % TG2;
    int c = (idx / TG2) % CH;
    int b = idx / (TG2 * CH);
    int py = q / TG, px = q % TG;
    size_t base = (size_t)b * CHW + (size_t)c * HW + (size_t)(py * 8) * IMG + px * 8;
    float sq = 0.f, sk = 0.f, sv = 0.f;
#pragma unroll
    for (int dy = 0; dy < 8; dy++) {
        size_t r = base + (size_t)dy * IMG;
#pragma unroll
        for (int dx = 0; dx < 8; dx++) {
            sq += g_q[r + dx]; sk += g_k[r + dx]; sv += g_v[r + dx];
        }
    }
    g_qg[idx] = sq * (1.f / 64.f);
    g_kg[idx] = sk * (1.f / 64.f);
    g_vg[idx] = sv * (1.f / 64.f);
}

// ---------------- 5) patch gram partials: wm_part = Qf^T Kf over s-split ----
__global__ __launch_bounds__(256) void k_wmgram() {
    int quarter = blockIdx.x & 3;     // p-quarter (49 each)
    int split = blockIdx.x >> 2;      // 0..127
    int b = blockIdx.y;
    const float* qf = g_q + (size_t)b * CHW;
    const float* kf = g_k + (size_t)b * CHW;
    __shared__ float qs[16][64];      // [s][p], 49 valid cols
    __shared__ float ks[16][208];     // [s][q], 196 valid cols
    int tx = threadIdx.x, ty = threadIdx.y;
    int tid = ty * 16 + tx;
    int p0 = quarter * 49;
    int s0 = split * SPLIT_LEN;

    float acc[4][13];
#pragma unroll
    for (int i = 0; i < 4; i++)
#pragma unroll
        for (int j = 0; j < 13; j++) acc[i][j] = 0.f;

    for (int kc = 0; kc < SPLIT_LEN; kc += 16) {
        for (int e = tid; e < 16 * 49; e += 256) {
            int r = e / 49, p = e % 49;
            qs[r][p] = qf[(size_t)(s0 + kc + r) * P2 + p0 + p];
        }
        for (int e = tid; e < 16 * P2; e += 256) {
            int r = e / P2, qq = e % P2;
            ks[r][qq] = kf[(size_t)(s0 + kc + r) * P2 + qq];
        }
        __syncthreads();
#pragma unroll 4
        for (int r = 0; r < 16; r++) {
            float a[4], bb[13];
#pragma unroll
            for (int i = 0; i < 4; i++) a[i] = qs[r][ty + 16 * i];
#pragma unroll
            for (int j = 0; j < 13; j++) bb[j] = ks[r][tx + 16 * j];
#pragma unroll
            for (int i = 0; i < 4; i++)
#pragma unroll
                for (int j = 0; j < 13; j++) acc[i][j] += a[i] * bb[j];
        }
        __syncthreads();
    }

    float* out = g_wmpart + ((size_t)(b * KSPLIT + split)) * WMN;
#pragma unroll
    for (int i = 0; i < 4; i++) {
        int pl = ty + 16 * i;
        if (pl < 49) {
#pragma unroll
            for (int j = 0; j < 13; j++) {
                int q = tx + 16 * j;
                if (q < P2) out[(size_t)(p0 + pl) * P2 + q] = acc[i][j];
            }
        }
    }
}

// ---------------- 6) reduce split partials + scale + softmax (rows of 196) --
__global__ void k_wmsoftmax() {
    int row = blockIdx.x;             // b*196 + p
    int b = row / P2;
    int p = row % P2;
    int t = threadIdx.x;
    float val = 0.f;
    if (t < P2) {
        const float* part = g_wmpart + (size_t)b * KSPLIT * WMN + (size_t)p * P2 + t;
        float s = 0.f;
        for (int sp = 0; sp < KSPLIT; sp++) s += part[(size_t)sp * WMN];
        val = s * (1.f / 256.f);      // S^-0.5, S=65536
    }
    __shared__ float sh[256];
    sh[t] = (t < P2) ? val : -INFINITY;
    __syncthreads();
    for (int o = 128; o > 0; o >>= 1) {
        if (t < o) sh[t] = fmaxf(sh[t], sh[t + o]);
        __syncthreads();
    }
    float mx = sh[0];
    __syncthreads();
    float e = (t < P2) ? expf(val - mx) : 0.f;
    sh[t] = e;
    __syncthreads();
    for (int o = 128; o > 0; o >>= 1) {
        if (t < o) sh[t] += sh[t + o];
        __syncthreads();
    }
    float inv = 1.f / sh[0];
    if (t < P2) g_wm[(size_t)row * P2 + t] = e * inv;
}

// ---------------- 7) hp[s,q] = sum_k vf[s,k] * wm[q,k] ----------------------
__global__ __launch_bounds__(256) void k_hp() {
    int b = blockIdx.y;
    int s0 = blockIdx.x * 64;
    const float* vf = g_v + (size_t)b * CHW;
    const float* wm = g_wm + (size_t)b * WMN;
    __shared__ float vs[28][65];      // [k][s_local]
    __shared__ float ws[28][209];     // [k][q]
    int tx = threadIdx.x, ty = threadIdx.y;
    int tid = ty * 16 + tx;

    float acc[4][13];
#pragma unroll
    for (int i = 0; i < 4; i++)
#pragma unroll
        for (int j = 0; j < 13; j++) acc[i][j] = 0.f;

    for (int k0 = 0; k0 < P2; k0 += 28) {
        for (int e = tid; e < 64 * 28; e += 256) {
            int sl = e / 28, kk = e % 28;
            vs[kk][sl] = vf[(size_t)(s0 + sl) * P2 + k0 + kk];
        }
        for (int e = tid; e < P2 * 28; e += 256) {
            int q = e / 28, kk = e % 28;
            ws[kk][q] = wm[(size_t)q * P2 + k0 + kk];
        }
        __syncthreads();
#pragma unroll 4
        for (int kk = 0; kk < 28; kk++) {
            float a[4], bb[13];
#pragma unroll
            for (int i = 0; i < 4; i++) a[i] = vs[kk][ty + 16 * i];
#pragma unroll
            for (int j = 0; j < 13; j++) bb[j] = ws[kk][tx + 16 * j];
#pragma unroll
            for (int i = 0; i < 4; i++)
#pragma unroll
                for (int j = 0; j < 13; j++) acc[i][j] += a[i] * bb[j];
        }
        __syncthreads();
    }

    float* hp = g_hp + (size_t)b * CHW + (size_t)s0 * P2;
#pragma unroll
    for (int i = 0; i < 4; i++) {
        int sl = ty + 16 * i;
#pragma unroll
        for (int j = 0; j < 13; j++) {
            int q = tx + 16 * j;
            if (q < P2) hp[(size_t)sl * P2 + q] = acc[i][j];
        }
    }
}

// ---------------- 8) global gram: wg[p,q] = (1/8) sum_c qg[c,p] kg[c,q] -----
__global__ __launch_bounds__(256) void k_wggram() {
    int pt = blockIdx.x / 49;
    int qt = blockIdx.x % 49;
    int b = blockIdx.y;
    const float* qg = g_qg + (size_t)b * CH * TG2;
    const float* kg = g_kg + (size_t)b * CH * TG2;
    __shared__ float qs[64][64];      // [c][p]
    __shared__ float ks[64][64];      // [c][q]
    int tx = threadIdx.x, ty = threadIdx.y;
    int tid = ty * 16 + tx;
    for (int e = tid; e < 4096; e += 256) {
        int c = e >> 6, l = e & 63;
        qs[c][l] = qg[(size_t)c * TG2 + pt * 64 + l];
        ks[c][l] = kg[(size_t)c * TG2 + qt * 64 + l];
    }
    __syncthreads();
    float acc[4][4];
#pragma unroll
    for (int i = 0; i < 4; i++)
#pragma unroll
        for (int j = 0; j < 4; j++) acc[i][j] = 0.f;
#pragma unroll 8
    for (int k = 0; k < 64; k++) {
        float a[4], bb[4];
#pragma unroll
        for (int i = 0; i < 4; i++) a[i] = qs[k][ty + 16 * i];
#pragma unroll
        for (int j = 0; j < 4; j++) bb[j] = ks[k][tx + 16 * j];
#pragma unroll
        for (int i = 0; i < 4; i++)
#pragma unroll
            for (int j = 0; j < 4; j++) acc[i][j] += a[i] * bb[j];
    }
    float* out = g_wg + (size_t)b * WGN;
#pragma unroll
    for (int i = 0; i < 4; i++) {
        int p = pt * 64 + ty + 16 * i;
#pragma unroll
        for (int j = 0; j < 4; j++) {
            int q = qt * 64 + tx + 16 * j;
            out[(size_t)p * TG2 + q] = acc[i][j] * 0.125f;   // c^-0.5
        }
    }
}

// ---------------- 9) softmax over rows of length 3136 -----------------------
__global__ void k_wgsoftmax() {
    int row = blockIdx.x;             // 0 .. B*TG2-1
    float* w = g_wg + (size_t)row * TG2;
    int t = threadIdx.x;
    float vals[13];
    float mx = -INFINITY;
#pragma unroll
    for (int i = 0; i < 13; i++) {
        int idx = t + 256 * i;
        vals[i] = (idx < TG2) ? w[idx] : -INFINITY;
        mx = fmaxf(mx, vals[i]);
    }
    __shared__ float sh[256];
    sh[t] = mx;
    __syncthreads();
    for (int o = 128; o > 0; o >>= 1) {
        if (t < o) sh[t] = fmaxf(sh[t], sh[t + o]);
        __syncthreads();
    }
    mx = sh[0];
    __syncthreads();
    float s = 0.f;
#pragma unroll
    for (int i = 0; i < 13; i++) {
        int idx = t + 256 * i;
        if (idx < TG2) {
            vals[i] = expf(vals[i] - mx);
            s += vals[i];
        }
    }
    sh[t] = s;
    __syncthreads();
    for (int o = 128; o > 0; o >>= 1) {
        if (t < o) sh[t] += sh[t + o];
        __syncthreads();
    }
    float inv = 1.f / sh[0];
#pragma unroll
    for (int i = 0; i < 13; i++) {
        int idx = t + 256 * i;
        if (idx < TG2) w[idx] = vals[i] * inv;
    }
}

// ---------------- 10) hg partials: hg[c,q] = sum_k vg[c,k] wg[q,k] ----------
__global__ __launch_bounds__(256) void k_hg() {
    int qt = blockIdx.x / 4;
    int sp = blockIdx.x % 4;          // k-split
    int b = blockIdx.y;
    const float* vg = g_vg + (size_t)b * CH * TG2;
    const float* wg = g_wg + (size_t)b * WGN;
    __shared__ float vs[16][65];      // [k][c]
    __shared__ float ws[16][65];      // [k][q_local]
    int tx = threadIdx.x, ty = threadIdx.y;
    int tid = ty * 16 + tx;

    float acc[4][4];
#pragma unroll
    for (int i = 0; i < 4; i++)
#pragma unroll
        for (int j = 0; j < 4; j++) acc[i][j] = 0.f;

    int kbase = sp * 784;
    for (int k0 = kbase; k0 < kbase + 784; k0 += 16) {
        for (int e = tid; e < 64 * 16; e += 256) {
            int c = e / 16, kk = e % 16;
            vs[kk][c] = vg[(size_t)c * TG2 + k0 + kk];
        }
        for (int e = tid; e < 64 * 16; e += 256) {
            int ql = e / 16, kk = e % 16;
            ws[kk][ql] = wg[(size_t)(qt * 64 + ql) * TG2 + k0 + kk];
        }
        __syncthreads();
#pragma unroll 4
        for (int kk = 0; kk < 16; kk++) {
            float a[4], bb[4];
#pragma unroll
            for (int i = 0; i < 4; i++) a[i] = vs[kk][ty + 16 * i];
#pragma unroll
            for (int j = 0; j < 4; j++) bb[j] = ws[kk][tx + 16 * j];
#pragma unroll
            for (int i = 0; i < 4; i++)
#pragma unroll
                for (int j = 0; j < 4; j++) acc[i][j] += a[i] * bb[j];
        }
        __syncthreads();
    }

    float* out = g_hgpart + (size_t)(b * 4 + sp) * CH * TG2;
#pragma unroll
    for (int i = 0; i < 4; i++) {
        int c = ty + 16 * i;
#pragma unroll
        for (int j = 0; j < 4; j++) {
            int q = qt * 64 + tx + 16 * j;
            out[(size_t)c * TG2 + q] = acc[i][j];
        }
    }
}

__global__ void k_hgreduce() {
    int idx = blockIdx.x * 256 + threadIdx.x;
    if (idx >= BATCH * CH * TG2) return;
    int b = idx / (CH * TG2);
    int r = idx % (CH * TG2);
    float s = 0.f;
#pragma unroll
    for (int sp = 0; sp < 4; sp++)
        s += g_hgpart[(size_t)(b * 4 + sp) * CH * TG2 + r];
    g_hg[idx] = s;
}

// ---------------- 11) final: out = x + proj_w @ (0.75 hp + 0.25 up(hg)) -----
__global__ __launch_bounds__(256) void k_final(
    const float* __restrict__ x,
    const float* __restrict__ pw,
    float* __restrict__ out) {
    __shared__ float Wt[64][64];      // [k][m]
    __shared__ float Hs[64][128];     // [k][n]
    int n0 = blockIdx.x * 128;
    int b = n0 / HW;
    int pix0 = n0 % HW;
    int tx = threadIdx.x, ty = threadIdx.y;
    int tid = ty * 16 + tx;

    for (int e = tid; e < 4096; e += 256) {
        int m = e >> 6, k = e & 63;
        Wt[k][m] = pw[e];
    }
    for (int e = tid; e < 8192; e += 256) {
        int k = e >> 7, nl = e & 127;
        int pix = pix0 + nl;
        int py = pix / IMG, px = pix % IMG;
        float hpv = g_hp[(size_t)b * CHW + (size_t)k * HW + pix];
        float hgv = g_hg[((size_t)b * CH + k) * TG2 + (py >> 3) * TG + (px >> 3)];
        Hs[k][nl] = 0.75f * hpv + 0.25f * hgv;
    }
    __syncthreads();

    float acc[4][8];
#pragma unroll
    for (int i = 0; i < 4; i++)
#pragma unroll
        for (int j = 0; j < 8; j++) acc[i][j] = 0.f;
#pragma unroll 8
    for (int k = 0; k < 64; k++) {
        float a[4], bb[8];
#pragma unroll
        for (int i = 0; i < 4; i++) a[i] = Wt[k][ty + 16 * i];
#pragma unroll
        for (int j = 0; j < 8; j++) bb[j] = Hs[k][tx + 16 * j];
#pragma unroll
        for (int i = 0; i < 4; i++)
#pragma unroll
            for (int j = 0; j < 8; j++) acc[i][j] += a[i] * bb[j];
    }

#pragma unroll
    for (int i = 0; i < 4; i++) {
        int m = ty + 16 * i;
#pragma unroll
        for (int j = 0; j < 8; j++) {
            size_t idx = (size_t)b * CHW + (size_t)m * HW + pix0 + tx + 16 * j;
            out[idx] = x[idx] + acc[i][j];
        }
    }
}

// ---------------- launch -----------------------------------------------------
extern "C" void kernel_launch(void* const* d_in, const int* in_sizes, int n_in,
                              void* d_out, int out_size) {
    const float* x   = (const float*)d_in[0];
    const float* gnw = (const float*)d_in[1];
    const float* gnb = (const float*)d_in[2];
    const float* qw  = (const float*)d_in[3];
    const float* qb  = (const float*)d_in[4];
    const float* kw  = (const float*)d_in[5];
    const float* kb  = (const float*)d_in[6];
    const float* vw  = (const float*)d_in[7];
    const float* vb  = (const float*)d_in[8];
    const float* pw  = (const float*)d_in[9];
    float* out = (float*)d_out;

    k_red1<<<dim3(1024, BATCH), 256>>>(x);
    k_red2<<<BATCH, 256>>>();
    k_gnqkv<<<dim3(3136, 3), dim3(16, 16)>>>(x, gnw, gnb, qw, qb, kw, kb, vw, vb);
    k_pool<<<1568, 256>>>();
    k_wmgram<<<dim3(4 * KSPLIT, BATCH), dim3(16, 16)>>>();
    k_wmsoftmax<<<BATCH * P2, 256>>>();
    k_hp<<<dim3(1024, BATCH), dim3(16, 16)>>>();
    k_wggram<<<dim3(49 * 49, BATCH), dim3(16, 16)>>>();
    k_wgsoftmax<<<BATCH * TG2, 256>>>();
    k_hg<<<dim3(49 * 4, BATCH), dim3(16, 16)>>>();
    k_hgreduce<<<1568, 256>>>();
    k_final<<<3136, dim3(16, 16)>>>(x, pw, out);
}

// round 16
// speedup vs baseline: 1.0041x; 1.0023x over previous
#include <cuda_runtime.h>
#include <math.h>

#define BATCH 2
#define CH 64
#define IMG 448
#define HW 200704            // 448*448
#define CHW 12845056         // 64*HW
#define P2 196
#define TG 56
#define TG2 3136
#define EPSV 1e-5f
#define KSPLIT 128
#define SPLIT_LEN 512        // 65536/128
#define WMN 38416            // 196*196
#define WGN 9834496          // 3136*3136

// ---------------- scratch (device globals; no allocations allowed) ----------
__device__ float g_q[BATCH * CHW];
__device__ float g_k[BATCH * CHW];
__device__ float g_v[BATCH * CHW];
__device__ float g_hp[BATCH * CHW];
__device__ float g_wm[BATCH * WMN];
__device__ float g_wmpart[BATCH * KSPLIT * WMN];
__device__ float g_wg[BATCH * WGN];
__device__ float g_qg[BATCH * CH * TG2];
__device__ float g_kg[BATCH * CH * TG2];
__device__ float g_vg[BATCH * CH * TG2];
__device__ float g_hgpart[BATCH * 4 * CH * TG2];
__device__ float g_hg[BATCH * CH * TG2];
__device__ float g_red[4096];   // [2 arrays][batch][1024 blocks]
__device__ float g_stats[4];    // mean,rstd per batch

// ---------------- 1) GroupNorm stats: partial reduction ---------------------
__global__ void k_red1(const float* __restrict__ x) {
    int b = blockIdx.y;
    int blk = blockIdx.x;                 // 0..1023
    const float* p = x + (size_t)b * CHW + (size_t)blk * 12544;
    float s = 0.f, s2 = 0.f;
    for (int i = threadIdx.x; i < 12544; i += 256) {
        float v = p[i];
        s += v; s2 += v * v;
    }
    __shared__ float sh0[256], sh1[256];
    sh0[threadIdx.x] = s; sh1[threadIdx.x] = s2;
    __syncthreads();
    for (int o = 128; o > 0; o >>= 1) {
        if (threadIdx.x < o) {
            sh0[threadIdx.x] += sh0[threadIdx.x + o];
            sh1[threadIdx.x] += sh1[threadIdx.x + o];
        }
        __syncthreads();
    }
    if (threadIdx.x == 0) {
        g_red[b * 1024 + blk] = sh0[0];
        g_red[2048 + b * 1024 + blk] = sh1[0];
    }
}

// ---------------- 2) finalize mean / rstd -----------------------------------
__global__ void k_red2() {
    int b = blockIdx.x;
    float s = 0.f, s2 = 0.f;
    for (int i = threadIdx.x; i < 1024; i += 256) {
        s += g_red[b * 1024 + i];
        s2 += g_red[2048 + b * 1024 + i];
    }
    __shared__ float sh0[256], sh1[256];
    sh0[threadIdx.x] = s; sh1[threadIdx.x] = s2;
    __syncthreads();
    for (int o = 128; o > 0; o >>= 1) {
        if (threadIdx.x < o) {
            sh0[threadIdx.x] += sh0[threadIdx.x + o];
            sh1[threadIdx.x] += sh1[threadIdx.x + o];
        }
        __syncthreads();
    }
    if (threadIdx.x == 0) {
        float mean = sh0[0] / (float)CHW;
        float var = sh1[0] / (float)CHW - mean * mean;
        g_stats[b * 2 + 0] = mean;
        g_stats[b * 2 + 1] = rsqrtf(var + EPSV);
    }
}

// ---------------- 3) fused GroupNorm + QKV (three 64x64 GEMMs over pixels) --
// Out[m, n] = W[m,:] . xn[:, n] + bias[m]; grid.y selects q/k/v.
__global__ __launch_bounds__(256) void k_gnqkv(
    const float* __restrict__ x,
    const float* __restrict__ gnw, const float* __restrict__ gnb,
    const float* __restrict__ qw, const float* __restrict__ qb,
    const float* __restrict__ kw, const float* __restrict__ kb,
    const float* __restrict__ vw, const float* __restrict__ vb) {
    __shared__ float Wt[64][64];    // [k][m]
    __shared__ float Xn[64][128];   // [k][n]
    int mt = blockIdx.y;
    int n0 = blockIdx.x * 128;      // global pixel index across batches
    int b = n0 / HW;
    int pix0 = n0 % HW;
    const float* W    = (mt == 0) ? qw : (mt == 1) ? kw : vw;
    const float* bias = (mt == 0) ? qb : (mt == 1) ? kb : vb;
    float* out = ((mt == 0) ? g_q : (mt == 1) ? g_k : g_v) + (size_t)b * CHW + pix0;

    float mean = g_stats[b * 2 + 0];
    float rstd = g_stats[b * 2 + 1];
    int tx = threadIdx.x, ty = threadIdx.y;
    int tid = ty * 16 + tx;

    for (int e = tid; e < 4096; e += 256) {
        int m = e >> 6, k = e & 63;
        Wt[k][m] = W[e];            // W is [m][k] row-major
    }
    const float* xb = x + (size_t)b * CHW + pix0;
    for (int e = tid; e < 8192; e += 256) {
        int k = e >> 7, nl = e & 127;
        float v = xb[(size_t)k * HW + nl];
        Xn[k][nl] = (v - mean) * rstd * gnw[k] + gnb[k];
    }
    __syncthreads();

    float acc[4][8];
#pragma unroll
    for (int i = 0; i < 4; i++)
#pragma unroll
        for (int j = 0; j < 8; j++) acc[i][j] = 0.f;

#pragma unroll 8
    for (int k = 0; k < 64; k++) {
        float a[4], bb[8];
#pragma unroll
        for (int i = 0; i < 4; i++) a[i] = Wt[k][ty + 16 * i];
#pragma unroll
        for (int j = 0; j < 8; j++) bb[j] = Xn[k][tx + 16 * j];
#pragma unroll
        for (int i = 0; i < 4; i++)
#pragma unroll
            for (int j = 0; j < 8; j++) acc[i][j] += a[i] * bb[j];
    }

#pragma unroll
    for (int i = 0; i < 4; i++) {
        int m = ty + 16 * i;
        float bv = bias[m];
#pragma unroll
        for (int j = 0; j < 8; j++)
            out[(size_t)m * HW + tx + 16 * j] = acc[i][j] + bv;
    }
}

// ---------------- 4) 8x8 average pool of q,k,v ------------------------------
__global__ void k_pool() {
    int idx = blockIdx.x * 256 + threadIdx.x;     // 0 .. B*C*TG2-1
    if (idx >= BATCH * CH * TG2) return;
    int q = idx % TG2;
    int c = (idx / TG2) % CH;
    int b = idx / (TG2 * CH);
    int py = q / TG, px = q % TG;
    size_t base = (size_t)b * CHW + (size_t)c * HW + (size_t)(py * 8) * IMG + px * 8;
    float sq = 0.f, sk = 0.f, sv = 0.f;
#pragma unroll
    for (int dy = 0; dy < 8; dy++) {
        size_t r = base + (size_t)dy * IMG;
#pragma unroll
        for (int dx = 0; dx < 8; dx++) {
            sq += g_q[r + dx]; sk += g_k[r + dx]; sv += g_v[r + dx];
        }
    }
    g_qg[idx] = sq * (1.f / 64.f);
    g_kg[idx] = sk * (1.f / 64.f);
    g_vg[idx] = sv * (1.f / 64.f);
}

// ---------------- 5) patch gram partials: wm_part = Qf^T Kf over s-split ----
__global__ __launch_bounds__(256) void k_wmgram() {
    int quarter = blockIdx.x & 3;     // p-quarter (49 each)
    int split = blockIdx.x >> 2;      // 0..127
    int b = blockIdx.y;
    const float* qf = g_q + (size_t)b * CHW;
    const float* kf = g_k + (size_t)b * CHW;
    __shared__ float qs[16][64];      // [s][p], 49 valid cols
    __shared__ float ks[16][208];     // [s][q], 196 valid cols
    int tx = threadIdx.x, ty = threadIdx.y;
    int tid = ty * 16 + tx;
    int p0 = quarter * 49;
    int s0 = split * SPLIT_LEN;

    float acc[4][13];
#pragma unroll
    for (int i = 0; i < 4; i++)
#pragma unroll
        for (int j = 0; j < 13; j++) acc[i][j] = 0.f;

    for (int kc = 0; kc < SPLIT_LEN; kc += 16) {
        for (int e = tid; e < 16 * 49; e += 256) {
            int r = e / 49, p = e % 49;
            qs[r][p] = qf[(size_t)(s0 + kc + r) * P2 + p0 + p];
        }
        for (int e = tid; e < 16 * P2; e += 256) {
            int r = e / P2, qq = e % P2;
            ks[r][qq] = kf[(size_t)(s0 + kc + r) * P2 + qq];
        }
        __syncthreads();
#pragma unroll 4
        for (int r = 0; r < 16; r++) {
            float a[4], bb[13];
#pragma unroll
            for (int i = 0; i < 4; i++) a[i] = qs[r][ty + 16 * i];
#pragma unroll
            for (int j = 0; j < 13; j++) bb[j] = ks[r][tx + 16 * j];
#pragma unroll
            for (int i = 0; i < 4; i++)
#pragma unroll
                for (int j = 0; j < 13; j++) acc[i][j] += a[i] * bb[j];
        }
        __syncthreads();
    }

    float* out = g_wmpart + ((size_t)(b * KSPLIT + split)) * WMN;
#pragma unroll
    for (int i = 0; i < 4; i++) {
        int pl = ty + 16 * i;
        if (pl < 49) {
#pragma unroll
            for (int j = 0; j < 13; j++) {
                int q = tx + 16 * j;
                if (q < P2) out[(size_t)(p0 + pl) * P2 + q] = acc[i][j];
            }
        }
    }
}

// ---------------- 6) reduce split partials + scale + softmax (rows of 196) --
__global__ void k_wmsoftmax() {
    int row = blockIdx.x;             // b*196 + p
    int b = row / P2;
    int p = row % P2;
    int t = threadIdx.x;
    float val = 0.f;
    if (t < P2) {
        const float* part = g_wmpart + (size_t)b * KSPLIT * WMN + (size_t)p * P2 + t;
        float s = 0.f;
        for (int sp = 0; sp < KSPLIT; sp++) s += part[(size_t)sp * WMN];
        val = s * (1.f / 256.f);      // S^-0.5, S=65536
    }
    __shared__ float sh[256];
    sh[t] = (t < P2) ? val : -INFINITY;
    __syncthreads();
    for (int o = 128; o > 0; o >>= 1) {
        if (t < o) sh[t] = fmaxf(sh[t], sh[t + o]);
        __syncthreads();
    }
    float mx = sh[0];
    __syncthreads();
    float e = (t < P2) ? expf(val - mx) : 0.f;
    sh[t] = e;
    __syncthreads();
    for (int o = 128; o > 0; o >>= 1) {
        if (t < o) sh[t] += sh[t + o];
        __syncthreads();
    }
    float inv = 1.f / sh[0];
    if (t < P2) g_wm[(size_t)row * P2 + t] = e * inv;
}

// ---------------- 7) hp[s,q] = sum_k vf[s,k] * wm[q,k] ----------------------
__global__ __launch_bounds__(256) void k_hp() {
    int b = blockIdx.y;
    int s0 = blockIdx.x * 64;
    const float* vf = g_v + (size_t)b * CHW;
    const float* wm = g_wm + (size_t)b * WMN;
    __shared__ float vs[28][65];      // [k][s_local]
    __shared__ float ws[28][209];     // [k][q]
    int tx = threadIdx.x, ty = threadIdx.y;
    int tid = ty * 16 + tx;

    float acc[4][13];
#pragma unroll
    for (int i = 0; i < 4; i++)
#pragma unroll
        for (int j = 0; j < 13; j++) acc[i][j] = 0.f;

    for (int k0 = 0; k0 < P2; k0 += 28) {
        for (int e = tid; e < 64 * 28; e += 256) {
            int sl = e / 28, kk = e % 28;
            vs[kk][sl] = vf[(size_t)(s0 + sl) * P2 + k0 + kk];
        }
        for (int e = tid; e < P2 * 28; e += 256) {
            int q = e / 28, kk = e % 28;
            ws[kk][q] = wm[(size_t)q * P2 + k0 + kk];
        }
        __syncthreads();
#pragma unroll 4
        for (int kk = 0; kk < 28; kk++) {
            float a[4], bb[13];
#pragma unroll
            for (int i = 0; i < 4; i++) a[i] = vs[kk][ty + 16 * i];
#pragma unroll
            for (int j = 0; j < 13; j++) bb[j] = ws[kk][tx + 16 * j];
#pragma unroll
            for (int i = 0; i < 4; i++)
#pragma unroll
                for (int j = 0; j < 13; j++) acc[i][j] += a[i] * bb[j];
        }
        __syncthreads();
    }

    float* hp = g_hp + (size_t)b * CHW + (size_t)s0 * P2;
#pragma unroll
    for (int i = 0; i < 4; i++) {
        int sl = ty + 16 * i;
#pragma unroll
        for (int j = 0; j < 13; j++) {
            int q = tx + 16 * j;
            if (q < P2) hp[(size_t)sl * P2 + q] = acc[i][j];
        }
    }
}

// ---------------- 8) global gram: wg[p,q] = (1/8) sum_c qg[c,p] kg[c,q] -----
__global__ __launch_bounds__(256) void k_wggram() {
    int pt = blockIdx.x / 49;
    int qt = blockIdx.x % 49;
    int b = blockIdx.y;
    const float* qg = g_qg + (size_t)b * CH * TG2;
    const float* kg = g_kg + (size_t)b * CH * TG2;
    __shared__ float qs[64][64];      // [c][p]
    __shared__ float ks[64][64];      // [c][q]
    int tx = threadIdx.x, ty = threadIdx.y;
    int tid = ty * 16 + tx;
    for (int e = tid; e < 4096; e += 256) {
        int c = e >> 6, l = e & 63;
        qs[c][l] = qg[(size_t)c * TG2 + pt * 64 + l];
        ks[c][l] = kg[(size_t)c * TG2 + qt * 64 + l];
    }
    __syncthreads();
    float acc[4][4];
#pragma unroll
    for (int i = 0; i < 4; i++)
#pragma unroll
        for (int j = 0; j < 4; j++) acc[i][j] = 0.f;
#pragma unroll 8
    for (int k = 0; k < 64; k++) {
        float a[4], bb[4];
#pragma unroll
        for (int i = 0; i < 4; i++) a[i] = qs[k][ty + 16 * i];
#pragma unroll
        for (int j = 0; j < 4; j++) bb[j] = ks[k][tx + 16 * j];
#pragma unroll
        for (int i = 0; i < 4; i++)
#pragma unroll
            for (int j = 0; j < 4; j++) acc[i][j] += a[i] * bb[j];
    }
    float* out = g_wg + (size_t)b * WGN;
#pragma unroll
    for (int i = 0; i < 4; i++) {
        int p = pt * 64 + ty + 16 * i;
#pragma unroll
        for (int j = 0; j < 4; j++) {
            int q = qt * 64 + tx + 16 * j;
            out[(size_t)p * TG2 + q] = acc[i][j] * 0.125f;   // c^-0.5
        }
    }
}

// ---------------- 9) softmax over rows of length 3136 -----------------------
__global__ void k_wgsoftmax() {
    int row = blockIdx.x;             // 0 .. B*TG2-1
    float* w = g_wg + (size_t)row * TG2;
    int t = threadIdx.x;
    float vals[13];
    float mx = -INFINITY;
#pragma unroll
    for (int i = 0; i < 13; i++) {
        int idx = t + 256 * i;
        vals[i] = (idx < TG2) ? w[idx] : -INFINITY;
        mx = fmaxf(mx, vals[i]);
    }
    __shared__ float sh[256];
    sh[t] = mx;
    __syncthreads();
    for (int o = 128; o > 0; o >>= 1) {
        if (t < o) sh[t] = fmaxf(sh[t], sh[t + o]);
        __syncthreads();
    }
    mx = sh[0];
    __syncthreads();
    float s = 0.f;
#pragma unroll
    for (int i = 0; i < 13; i++) {
        int idx = t + 256 * i;
        if (idx < TG2) {
            vals[i] = expf(vals[i] - mx);
            s += vals[i];
        }
    }
    sh[t] = s;
    __syncthreads();
    for (int o = 128; o > 0; o >>= 1) {
        if (t < o) sh[t] += sh[t + o];
        __syncthreads();
    }
    float inv = 1.f / sh[0];
#pragma unroll
    for (int i = 0; i < 13; i++) {
        int idx = t + 256 * i;
        if (idx < TG2) w[idx] = vals[i] * inv;
    }
}

// ---------------- 10) hg partials: hg[c,q] = sum_k vg[c,k] wg[q,k] ----------
__global__ __launch_bounds__(256) void k_hg() {
    int qt = blockIdx.x / 4;
    int sp = blockIdx.x % 4;          // k-split
    int b = blockIdx.y;
    const float* vg = g_vg + (size_t)b * CH * TG2;
    const float* wg = g_wg + (size_t)b * WGN;
    __shared__ float vs[16][65];      // [k][c]
    __shared__ float ws[16][65];      // [k][q_local]
    int tx = threadIdx.x, ty = threadIdx.y;
    int tid = ty * 16 + tx;

    float acc[4][4];
#pragma unroll
    for (int i = 0; i < 4; i++)
#pragma unroll
        for (int j = 0; j < 4; j++) acc[i][j] = 0.f;

    int kbase = sp * 784;
    for (int k0 = kbase; k0 < kbase + 784; k0 += 16) {
        for (int e = tid; e < 64 * 16; e += 256) {
            int c = e / 16, kk = e % 16;
            vs[kk][c] = vg[(size_t)c * TG2 + k0 + kk];
        }
        for (int e = tid; e < 64 * 16; e += 256) {
            int ql = e / 16, kk = e % 16;
            ws[kk][ql] = wg[(size_t)(qt * 64 + ql) * TG2 + k0 + kk];
        }
        __syncthreads();
#pragma unroll 4
        for (int kk = 0; kk < 16; kk++) {
            float a[4], bb[4];
#pragma unroll
            for (int i = 0; i < 4; i++) a[i] = vs[kk][ty + 16 * i];
#pragma unroll
            for (int j = 0; j < 4; j++) bb[j] = ws[kk][tx + 16 * j];
#pragma unroll
            for (int i = 0; i < 4; i++)
#pragma unroll
                for (int j = 0; j < 4; j++) acc[i][j] += a[i] * bb[j];
        }
        __syncthreads();
    }

    float* out = g_hgpart + (size_t)(b * 4 + sp) * CH * TG2;
#pragma unroll
    for (int i = 0; i < 4; i++) {
        int c = ty + 16 * i;
#pragma unroll
        for (int j = 0; j < 4; j++) {
            int q = qt * 64 + tx + 16 * j;
            out[(size_t)c * TG2 + q] = acc[i][j];
        }
    }
}

__global__ void k_hgreduce() {
    int idx = blockIdx.x * 256 + threadIdx.x;
    if (idx >= BATCH * CH * TG2) return;
    int b = idx / (CH * TG2);
    int r = idx % (CH * TG2);
    float s = 0.f;
#pragma unroll
    for (int sp = 0; sp < 4; sp++)
        s += g_hgpart[(size_t)(b * 4 + sp) * CH * TG2 + r];
    g_hg[idx] = s;
}

// ---------------- 11) final: out = x + proj_w @ (0.75 hp + 0.25 up(hg)) -----
__global__ __launch_bounds__(256) void k_final(
    const float* __restrict__ x,
    const float* __restrict__ pw,
    float* __restrict__ out) {
    __shared__ float Wt[64][64];      // [k][m]
    __shared__ float Hs[64][128];     // [k][n]
    int n0 = blockIdx.x * 128;
    int b = n0 / HW;
    int pix0 = n0 % HW;
    int tx = threadIdx.x, ty = threadIdx.y;
    int tid = ty * 16 + tx;

    for (int e = tid; e < 4096; e += 256) {
        int m = e >> 6, k = e & 63;
        Wt[k][m] = pw[e];
    }
    for (int e = tid; e < 8192; e += 256) {
        int k = e >> 7, nl = e & 127;
        int pix = pix0 + nl;
        int py = pix / IMG, px = pix % IMG;
        float hpv = g_hp[(size_t)b * CHW + (size_t)k * HW + pix];
        float hgv = g_hg[((size_t)b * CH + k) * TG2 + (py >> 3) * TG + (px >> 3)];
        Hs[k][nl] = 0.75f * hpv + 0.25f * hgv;
    }
    __syncthreads();

    float acc[4][8];
#pragma unroll
    for (int i = 0; i < 4; i++)
#pragma unroll
        for (int j = 0; j < 8; j++) acc[i][j] = 0.f;
#pragma unroll 8
    for (int k = 0; k < 64; k++) {
        float a[4], bb[8];
#pragma unroll
        for (int i = 0; i < 4; i++) a[i] = Wt[k][ty + 16 * i];
#pragma unroll
        for (int j = 0; j < 8; j++) bb[j] = Hs[k][tx + 16 * j];
#pragma unroll
        for (int i = 0; i < 4; i++)
#pragma unroll
            for (int j = 0; j < 8; j++) acc[i][j] += a[i] * bb[j];
    }

#pragma unroll
    for (int i = 0; i < 4; i++) {
        int m = ty + 16 * i;
#pragma unroll
        for (int j = 0; j < 8; j++) {
            size_t idx = (size_t)b * CHW + (size_t)m * HW + pix0 + tx + 16 * j;
            out[idx] = x[idx] + acc[i][j];
        }
    }
}

// ---------------- launch -----------------------------------------------------
extern "C" void kernel_launch(void* const* d_in, const int* in_sizes, int n_in,
                              void* d_out, int out_size) {
    const float* x   = (const float*)d_in[0];
    const float* gnw = (const float*)d_in[1];
    const float* gnb = (const float*)d_in[2];
    const float* qw  = (const float*)d_in[3];
    const float* qb  = (const float*)d_in[4];
    const float* kw  = (const float*)d_in[5];
    const float* kb  = (const float*)d_in[6];
    const float* vw  = (const float*)d_in[7];
    const float* vb  = (const float*)d_in[8];
    const float* pw  = (const float*)d_in[9];
    float* out = (float*)d_out;

    k_red1<<<dim3(1024, BATCH), 256>>>(x);
    k_red2<<<BATCH, 256>>>();
    k_gnqkv<<<dim3(3136, 3), dim3(16, 16)>>>(x, gnw, gnb, qw, qb, kw, kb, vw, vb);
    k_pool<<<1568, 256>>>();
    k_wmgram<<<dim3(4 * KSPLIT, BATCH), dim3(16, 16)>>>();
    k_wmsoftmax<<<BATCH * P2, 256>>>();
    k_hp<<<dim3(1024, BATCH), dim3(16, 16)>>>();
    k_wggram<<<dim3(49 * 49, BATCH), dim3(16, 16)>>>();
    k_wgsoftmax<<<BATCH * TG2, 256>>>();
    k_hg<<<dim3(49 * 4, BATCH), dim3(16, 16)>>>();
    k_hgreduce<<<1568, 256>>>();
    k_final<<<3136, dim3(16, 16)>>>(x, pw, out);
}